// round 12
// baseline (speedup 1.0000x reference)
#include <cuda_runtime.h>

#define BB 16
#define NN 576
#define MM 16
#define DD 81
#define BG 80
#define THR 0.75f
#define KIOU 0.42857142857f   // THR/(1+THR)
#define NSC 4                 // scan CTAs per batch
#define QPC 144               // queries per scan CTA
#define NSL 4                 // firer slices per query
#define NSTAT 4
#define RPS 144
#define RPW 8                 // rows per warp in stat blocks

// ---------------- global staging (rewritten / self-resetting each run) ----------------
__device__ float4   g_fb [BB][NSC][QPC];   // firer boxes per segment (single writer)
__device__ float2   g_fme[BB][NSC][QPC];   // (KIOU*area, idx-as-float-bits)
__device__ int      g_fcnt[BB][NSC];       // published counts   (reset by batch reducer)
__device__ int      g_prog[BB][NSC];       // consumed progress  (reset by batch reducer)
__device__ int      g_spar[BB][NN];        // pred forest (fully rewritten)
__device__ float    g_lse[BB][NN];
__device__ float    g_inv[BB][NN];
__device__ float    g_SallQ[BB][NSTAT][DD];
__device__ float    g_Pp [BB][NSC][DD];
__device__ float    g_Snp[BB][NSC][DD];
__device__ int      g_Cp [BB][NSC][DD];
__device__ float    g_cep[BB][NSC][3];     // flbg, flfg, cb partials
__device__ float    g_S[BB][DD], g_P[BB][DD];
__device__ int      g_C[BB][DD];
__device__ float    g_ce[BB], g_bb[BB], g_gi[BB];
__device__ unsigned g_sparr[BB];           // spar barrier (reset by batch reducer)
__device__ unsigned g_doneq[BB][NSTAT];    // stat done flags (CAS-consumed)
__device__ unsigned g_btick[BB];           // per-batch ticket (atomicInc wrap)
__device__ unsigned g_tick;                // global ticket (atomicInc wrap)

__device__ __forceinline__ float wsum(float v) {
    #pragma unroll
    for (int o = 16; o; o >>= 1) v += __shfl_xor_sync(0xffffffffu, v, o);
    return v;
}
__device__ __forceinline__ int4 poll4(const int* p) {
    int4 r;
    asm volatile("ld.global.cg.v4.b32 {%0,%1,%2,%3}, [%4];"
                 : "=r"(r.x), "=r"(r.y), "=r"(r.z), "=r"(r.w) : "l"(p));
    return r;
}

__global__ void __launch_bounds__(NN) k_main(
    const float* __restrict__ emb, const float* __restrict__ cp,
    const float* __restrict__ pb,  const float* __restrict__ tb,
    const int* __restrict__ tl,    const int* __restrict__ mi,
    float* __restrict__ out)
{
    const int j    = threadIdx.x;
    const int wid  = j >> 5;
    const int lane = j & 31;

    if (blockIdx.x >= BB*NSC) {
        // ================= STAT BLOCK: batch b, slice q (144 rows) =================
        const int sb = blockIdx.x - BB*NSC;
        const int b  = sb >> 2, q = sb & 3;
        __shared__ float sSall[DD];
        if (j < DD) sSall[j] = 0.f;
        __syncthreads();

        if (q == 0 && wid == 0) {   // bbox L1 + GIoU
            float l1 = 0.f, gi = 0.f;
            if (lane < MM) {
                int idx = mi[b*MM + lane];
                float4 s  = ((const float4*)pb)[b*NN + idx];
                float4 tg = ((const float4*)tb)[b*MM + lane];
                l1 = fabsf(s.x - tg.x) + fabsf(s.y - tg.y)
                   + fabsf(s.z - tg.z) + fabsf(s.w - tg.w);
                float lx = fmaxf(s.x, tg.x), ly = fmaxf(s.y, tg.y);
                float rx = fminf(s.z, tg.z), ry = fminf(s.w, tg.w);
                float w_ = fmaxf(rx - lx, 0.f), h_ = fmaxf(ry - ly, 0.f);
                float inter = w_ * h_;
                float areas = (s.z - s.x) * (s.w - s.y);
                float areat = (tg.z - tg.x) * (tg.w - tg.y);
                float uni = areas + areat - inter;
                float iou = inter / uni;
                float lx2 = fminf(s.x, tg.x), ly2 = fminf(s.y, tg.y);
                float rx2 = fmaxf(s.z, tg.z), ry2 = fmaxf(s.w, tg.w);
                float ac  = (rx2 - lx2) * (ry2 - ly2);
                gi = 1.f - (iou - (ac - uni) / ac);
            }
            l1 = wsum(l1); gi = wsum(gi);
            if (lane == 0) { g_bb[b] = l1; g_gi[b] = gi; }
        }

        const float* cpb = cp  + ((size_t)b*NN + q*RPS) * DD;
        const float* eb  = emb + ((size_t)b*NN + q*RPS) * DD;
        float aS0 = 0.f, aS1 = 0.f, aS2 = 0.f;
        #pragma unroll
        for (int r = 0; r < RPW; r++) {
            int i = wid * RPW + r;                 // local row 0..143
            const float* crow = cpb + (size_t)i * DD;
            const float* erow = eb  + (size_t)i * DD;
            float x0 = crow[lane];
            float x1 = crow[32 + lane];
            float x2 = (lane < 17) ? crow[64 + lane] : 0.f;
            float y0 = erow[lane];
            float y1 = erow[32 + lane];
            float y2 = (lane < 17) ? erow[64 + lane] : 0.f;
            float es = __expf(x0) + __expf(x1) + ((lane < 17) ? __expf(x2) : 0.f);
            float s  = wsum(es);
            float ss = wsum(y0*y0 + y1*y1 + y2*y2);
            float inv = rsqrtf(fmaxf(ss, 1e-24f));
            int gr = q * RPS + i;
            if (lane == 0) { g_lse[b][gr] = __logf(s); g_inv[b][gr] = inv; }
            aS0 += fmaxf(y0 * inv - 0.5f, 0.f);
            aS1 += fmaxf(y1 * inv - 0.5f, 0.f);
            if (lane < 17) aS2 += fmaxf(y2 * inv - 0.5f, 0.f);
        }
        atomicAdd(&sSall[lane],      aS0);
        atomicAdd(&sSall[lane + 32], aS1);
        if (lane < 17) atomicAdd(&sSall[lane + 64], aS2);
        __syncthreads();
        if (j < DD) g_SallQ[b][q][j] = sSall[j];
        __syncthreads();
        if (j == 0) { __threadfence(); atomicExch(&g_doneq[b][q], 1u); }
        return;
    }

    // ================= SCAN CTA: batch b, chunk c (queries [c*144,(c+1)*144)) =========
    const int b = blockIdx.x >> 2, c = blockIdx.x & 3;
    const int base  = c * QPC;
    const int q     = j % QPC;
    const int slice = j / QPC;
    const int qg    = base + q;
    const bool own  = (slice == 0);

    __shared__ float4 sfbox[NN];       // local concatenated firer list
    __shared__ float2 sfme[NN];
    __shared__ int    stc0[NN];
    __shared__ unsigned char sfired[QPC];
    __shared__ int    simax[QPC], spred[QPC];
    __shared__ float  sP[DD], sSn[DD];
    __shared__ int    sC[DD];
    __shared__ float  sfv[3];
    __shared__ int    s_apos, s_lcnt, s_done, s_new[NSC];
    __shared__ int    slast, sglast;
    __shared__ float  racc[3];

    float4 boxj = ((const float4*)pb)[b*NN + qg];
    float aj  = (boxj.z - boxj.x) * (boxj.w - boxj.y);
    float kaj = KIOU * aj;
    stc0[j] = BG;
    if (j < QPC) { sfired[j] = 0; simax[j] = -1; spred[j] = -1; }
    if (j < DD)  { sP[j] = 0.f; sSn[j] = 0.f; sC[j] = 0; }
    if (j < 3)   sfv[j] = 0.f;
    if (j == 0)  { s_apos = 0; s_lcnt = 0; s_done = 0; }
    __syncthreads();
    if (j == 0) {
        #pragma unroll
        for (int m = 0; m < MM; m++)
            stc0[mi[b*MM + m]] = tl[b*MM + m];   // last-wins scatter
    }
    __syncthreads();

    // seed appends (owner threads only; single writer per segment)
    bool app = false;
    if (own && stc0[qg] != BG) {
        app = true;
        int pos = atomicAdd(&s_apos, 1);
        g_fb[b][c][pos]  = boxj;
        g_fme[b][c][pos] = make_float2(kaj, __int_as_float(qg));
    }
    __syncthreads();
    if (j == 0) { __threadfence(); atomicExch(&g_fcnt[b][c], s_apos); }

    // ---- barrier-free monotone closure ----
    int imax = -1, pred = -1;
    int seen0 = 0, seen1 = 0, seen2 = 0, seen3 = 0;   // uniform across threads
    int seentot = 0;                                   // thread0's copy is authoritative
    for (;;) {
        if (j == 0) {
            for (;;) {
                int4 cc = poll4(&g_fcnt[b][0]);
                int tot = cc.x + cc.y + cc.z + cc.w;
                if (tot > seentot) {
                    s_new[0] = cc.x; s_new[1] = cc.y; s_new[2] = cc.z; s_new[3] = cc.w;
                    break;
                }
                int4 pp = poll4(&g_prog[b][0]);
                int mp = min(min(pp.x, pp.y), min(pp.z, pp.w));
                if (mp >= tot) {
                    int4 c2 = poll4(&g_fcnt[b][0]);
                    if (c2.x + c2.y + c2.z + c2.w == tot) { s_done = 1; break; }
                }
                __nanosleep(128);
            }
        }
        __syncthreads();
        if (s_done) break;

        int n0 = s_new[0], n1 = s_new[1], n2 = s_new[2], n3 = s_new[3];
        int d0 = n0 - seen0, d1 = n1 - seen1, d2 = n2 - seen2, d3 = n3 - seen3;
        int tnew = d0 + d1 + d2 + d3;
        int lbase = s_lcnt;

        // cooperative copy of new global entries into the local list
        for (int k = j; k < tnew; k += NN) {
            int s, idx;
            if      (k < d0)           { s = 0; idx = seen0 + k; }
            else if (k < d0+d1)        { s = 1; idx = seen1 + k - d0; }
            else if (k < d0+d1+d2)     { s = 2; idx = seen2 + k - d0 - d1; }
            else                       { s = 3; idx = seen3 + k - d0 - d1 - d2; }
            sfbox[lbase + k] = __ldcg(&g_fb[b][s][idx]);
            sfme [lbase + k] = __ldcg(&g_fme[b][s][idx]);
        }
        seen0 = n0; seen1 = n1; seen2 = n2; seen3 = n3;
        __syncthreads();

        // test new local range, slice-strided
        for (int fi = lbase + slice; fi < lbase + tnew; fi += NSL) {
            float4 be = sfbox[fi];
            float2 me = sfme[fi];
            float ke = me.x;
            int   e  = __float_as_int(me.y);
            float lx = fmaxf(be.x, boxj.x), ly = fmaxf(be.y, boxj.y);
            float rx = fminf(be.z, boxj.z), ry = fminf(be.w, boxj.w);
            float w_ = fmaxf(rx - lx, 0.f), h_ = fmaxf(ry - ly, 0.f);
            float inter = w_ * h_;
            if (inter > ke + kaj) {
                imax = max(imax, e);
                if (e < qg) { pred = max(pred, e); sfired[q] = 1; }
            }
        }
        __syncthreads();

        // owner appends newly fired queries
        if (own && sfired[q] && !app) {
            app = true;
            int pos = atomicAdd(&s_apos, 1);
            g_fb[b][c][pos]  = boxj;
            g_fme[b][c][pos] = make_float2(kaj, __int_as_float(qg));
        }
        __syncthreads();
        if (j == 0) {
            __threadfence();
            atomicExch(&g_fcnt[b][c], s_apos);
            seentot += tnew;
            atomicExch(&g_prog[b][c], seentot);
            s_lcnt = lbase + tnew;
        }
    }

    // combine per-slice imax/pred, publish pred forest
    if (imax >= 0) atomicMax(&simax[q], imax);
    if (pred >= 0) atomicMax(&spred[q], pred);
    __syncthreads();
    if (j < QPC) {
        int pr = spred[j];
        g_spar[b][base + j] = (pr >= 0) ? pr : (base + j);
    }
    __threadfence();
    __syncthreads();
    if (j == 0) {
        atomicAdd(&g_sparr[b], 1u);
        while (atomicCAS(&g_doneq[b][c], 1u, 0u) != 1u) __nanosleep(64);   // paired stats
        while (atomicAdd(&g_sparr[b], 0u) < (unsigned)NSC) __nanosleep(64);
        __threadfence();
    }
    __syncthreads();

    // ===== chase + B2 (owners j<144 carry real values; others contribute zeros) =====
    int   t   = BG;
    float fl = 0.f, e = 0.f;
    if (j < QPC) {
        int im = simax[j];
        if (im >= 0) {
            int p = im, pq2 = g_spar[b][p];
            while (pq2 != p) { p = pq2; pq2 = g_spar[b][p]; }
            t = stc0[p];
        }
        float lse = g_lse[b][base + j];
        float inv = g_inv[b][base + j];
        float xt = cp [(size_t)(b*NN + base + j) * DD + t];
        float yt = emb[(size_t)(b*NN + base + j) * DD + t];
        e = yt * inv;
        float ce = lse - xt;
        float p  = __expf(-ce);
        fl = (1.f - p) * (1.f - p) * ce;
    }
    {
        bool ownb = (j < QPC);
        bool isbg = ownb && (t == BG);
        bool isfg = ownb && (t != BG);
        float flbg = isbg ? 0.1f * fl : 0.f;
        float flfg = isfg ? fl : 0.f;
        float pcv  = isbg ? (1.f - e) : 0.f;
        float scv  = isbg ? fmaxf(e - 0.5f, 0.f) : 0.f;
        flbg = wsum(flbg); flfg = wsum(flfg);
        pcv  = wsum(pcv);  scv  = wsum(scv);
        unsigned bm = __ballot_sync(0xffffffffu, isbg);
        if (lane == 0) {
            atomicAdd(&sfv[0], flbg);
            atomicAdd(&sfv[1], flfg);
            atomicAdd(&sfv[2], (float)__popc(bm));
            atomicAdd(&sP[BG], pcv);
            atomicAdd(&sSn[BG], scv);
        }
        if (lane == 0) atomicAdd(&sC[BG], __popc(bm));
        if (isfg) {
            atomicAdd(&sP[t], 1.f - e);
            atomicAdd(&sSn[t], fmaxf(e - 0.5f, 0.f));
            atomicAdd(&sC[t], 1);
        }
    }
    __syncthreads();

    // publish per-CTA partials
    if (j < DD) {
        g_Pp [b][c][j] = sP[j];
        g_Snp[b][c][j] = sSn[j];
        g_Cp [b][c][j] = sC[j];
    }
    if (j == 0) {
        g_cep[b][c][0] = sfv[0];
        g_cep[b][c][1] = sfv[1];
        g_cep[b][c][2] = sfv[2];
    }
    __threadfence();
    __syncthreads();
    if (j == 0) {
        unsigned old = atomicInc(&g_btick[b], NSC - 1u);
        slast = (old == NSC - 1u) ? 1 : 0;
    }
    __syncthreads();
    if (!slast) return;
    __threadfence();

    // ===== batch reducer =====
    if (j < DD) {
        float S = 0.f, P = 0.f; int C = 0; float Sn = 0.f;
        #pragma unroll
        for (int k = 0; k < NSTAT; k++) S += g_SallQ[b][k][j];
        #pragma unroll
        for (int k = 0; k < NSC; k++) {
            P  += g_Pp [b][k][j];
            Sn += g_Snp[b][k][j];
            C  += g_Cp [b][k][j];
        }
        g_S[b][j] = S - Sn;
        g_P[b][j] = P;
        g_C[b][j] = C;
    }
    if (j == 0) {
        float fb = 0.f, ff = 0.f, cb = 0.f;
        #pragma unroll
        for (int k = 0; k < NSC; k++) {
            fb += g_cep[b][k][0]; ff += g_cep[b][k][1]; cb += g_cep[b][k][2];
        }
        g_ce[b] = fb / cb + ff / ((float)NN - cb);
        atomicExch(&g_sparr[b], 0u);               // reset for next run
    }
    if (j < NSC) {
        atomicExch(&g_fcnt[b][j], 0);
        atomicExch(&g_prog[b][j], 0);
    }
    __threadfence();
    __syncthreads();
    if (j == 0) {
        unsigned old = atomicInc(&g_tick, BB - 1u);
        sglast = (old == BB - 1u) ? 1 : 0;
    }
    __syncthreads();
    if (!sglast) return;
    __threadfence();

    if (j < 3) racc[j] = 0.f;
    __syncthreads();
    if (j < DD) {
        float C = 0.f, P = 0.f, S = 0.f;
        #pragma unroll
        for (int b2 = 0; b2 < BB; b2++) {
            C += (float)g_C[b2][j];
            P += g_P[b2][j];
            S += g_S[b2][j];
        }
        atomicAdd(&racc[0], C * C);
        atomicAdd(&racc[1], C * P);
        atomicAdd(&racc[2], C * S);
    }
    __syncthreads();
    if (j == 0) {
        float ces = 0.f, bbs = 0.f, gis = 0.f;
        #pragma unroll
        for (int b2 = 0; b2 < BB; b2++) { ces += g_ce[b2]; bbs += g_bb[b2]; gis += g_gi[b2]; }
        float pc = racc[0];
        float T  = (float)(BB * NN);
        float nc = T * T - pc;
        out[0] = ces / (float)BB;
        out[1] = (racc[1] / pc + racc[2] / nc) / (float)BB;
        out[2] = bbs / (float)(BB * MM);
        out[3] = gis / (float)(BB * MM);
    }
}

extern "C" void kernel_launch(void* const* d_in, const int* in_sizes, int n_in,
                              void* d_out, int out_size)
{
    const float* emb = (const float*)d_in[0];   // image_embeddings
    const float* cp  = (const float*)d_in[1];   // class_predictions
    const float* pb  = (const float*)d_in[2];   // pred_boxes
    const float* tb  = (const float*)d_in[3];   // target_boxes
    const int*   tl  = (const int*)  d_in[4];   // target_labels
    const int*   mi  = (const int*)  d_in[5];   // match_idx
    float* out = (float*)d_out;

    k_main<<<BB*NSC + BB*NSTAT, NN>>>(emb, cp, pb, tb, tl, mi, out);
}